// round 9
// baseline (speedup 1.0000x reference)
#include <cuda_runtime.h>
#include <cuda_fp16.h>
#include <cstdint>

#define NB 16
#define NN 128
#define NH 256

// ---------------- scratch (static, no runtime allocation) ----------------
__device__ float g_xwb[NB * NN * NH];                 // inputs@W_atom + 0.5*b_bin (fp32, 2 MB)
__device__ __align__(16) __half g_wbinT_h[NH * NH];   // W_bin transposed [n][h], fp16 (128 KB)

// ---------------- helpers ----------------
__device__ __forceinline__ uint32_t s2u(const void* p) {
    return (uint32_t)__cvta_generic_to_shared(p);
}
__device__ __forceinline__ void cp16(uint32_t d, const void* s) {
    asm volatile("cp.async.cg.shared.global [%0], [%1], 16;" :: "r"(d), "l"(s));
}
__device__ __forceinline__ void cp_commit() { asm volatile("cp.async.commit_group;"); }
template <int N> __device__ __forceinline__ void cp_wait() {
    asm volatile("cp.async.wait_group %0;" :: "n"(N));
}
__device__ __forceinline__ uint32_t packh2(float x, float y) {
    __half2 h = __floats2half2_rn(x, y);
    return *(uint32_t*)&h;
}
__device__ __forceinline__ void mma_f16(float* c, const uint32_t* a, uint32_t b0, uint32_t b1) {
    asm volatile(
        "mma.sync.aligned.m16n8k16.row.col.f32.f16.f16.f32 "
        "{%0,%1,%2,%3}, {%4,%5,%6,%7}, {%8,%9}, {%0,%1,%2,%3};"
        : "+f"(c[0]), "+f"(c[1]), "+f"(c[2]), "+f"(c[3])
        : "r"(a[0]), "r"(a[1]), "r"(a[2]), "r"(a[3]), "r"(b0), "r"(b1));
}

// ---------------- kernel 1: xwb = inputs@W_atom + 0.5*b_bin ; W_bin^T -> fp16 ----------------
__global__ __launch_bounds__(256) void k_prep(
    const float* __restrict__ inp, const float* __restrict__ Wa,
    const float* __restrict__ Wb, const float* __restrict__ bb)
{
    __shared__ float sh[2112];
    const int tid = threadIdx.x;
    const int bid = blockIdx.x;

    if (bid < 256) {
        const int base = bid * 8;
        for (int c = tid; c < 512; c += 256)
            ((float4*)sh)[c] = ((const float4*)(inp + (size_t)base * NH))[c];
        __syncthreads();

        const int quad = tid & 63;
        const int c0 = quad * 4;
        const int r0 = (tid >> 6) * 2;
        float acc0[4] = {0, 0, 0, 0}, acc1[4] = {0, 0, 0, 0};
        const float* s0 = sh + r0 * NH;
        const float* s1 = sh + (r0 + 1) * NH;
#pragma unroll 4
        for (int h = 0; h < NH; h++) {
            float4 w = *(const float4*)(Wa + (size_t)h * NH + c0);
            float a0 = s0[h], a1 = s1[h];
            acc0[0] = fmaf(a0, w.x, acc0[0]); acc0[1] = fmaf(a0, w.y, acc0[1]);
            acc0[2] = fmaf(a0, w.z, acc0[2]); acc0[3] = fmaf(a0, w.w, acc0[3]);
            acc1[0] = fmaf(a1, w.x, acc1[0]); acc1[1] = fmaf(a1, w.y, acc1[1]);
            acc1[2] = fmaf(a1, w.z, acc1[2]); acc1[3] = fmaf(a1, w.w, acc1[3]);
        }
        float4 bv = *(const float4*)(bb + c0);
        *(float4*)(g_xwb + (size_t)(base + r0) * NH + c0) =
            make_float4(acc0[0] + 0.5f * bv.x, acc0[1] + 0.5f * bv.y,
                        acc0[2] + 0.5f * bv.z, acc0[3] + 0.5f * bv.w);
        *(float4*)(g_xwb + (size_t)(base + r0 + 1) * NH + c0) =
            make_float4(acc1[0] + 0.5f * bv.x, acc1[1] + 0.5f * bv.y,
                        acc1[2] + 0.5f * bv.z, acc1[3] + 0.5f * bv.w);
    } else {
        // transpose 32x32 tile of W_bin -> g_wbinT_h[n][h] (fp16)
        const int t = bid - 256;
        const int nb = (t >> 3) * 32, hb = (t & 7) * 32;
        const int ty = tid >> 5, tx = tid & 31;
#pragma unroll
        for (int r = 0; r < 4; r++) {
            int hl = ty + r * 8;
            sh[hl * 33 + tx] = Wb[(size_t)(hb + hl) * NH + nb + tx];
        }
        __syncthreads();
#pragma unroll
        for (int r = 0; r < 4; r++) {
            int nl = ty + r * 8;
            g_wbinT_h[(size_t)(nb + nl) * NH + hb + tx] = __float2half_rn(sh[tx * 33 + nl]);
        }
    }
}

// ---------------- kernel 2: fp16 MMA GEMM + fused epilogue + atom_pair ----------------
// One CTA per (b,i): D[j,n] = sum_h bin[b,i,j,h]*W_bin[h,n], M=128, N=256, K=256.
// 1024 threads = 32 warps in 8(m) x 4(n); warp tile 16x64; acc = 32 regs/thread.
// K chunked by 32, double-buffered cp.async.
// SMEM: A f32 [2][128][144B] (36864), B fp16 [2][256][80B] (40960), sW 1KB, sXI 1KB.
// A stride 144B = 36 floats == 4 mod 32 banks -> g=0..7 rows hit distinct bank groups.
#define A_BUF   18432
#define B_BUF   20480
#define OFF_B   36864
#define OFF_W   77824
#define OFF_XI  78848
#define SMEM_MAIN 79872

__global__ __launch_bounds__(1024, 1) void k_main(
    const float* __restrict__ bin, const float* __restrict__ inp,
    const float* __restrict__ wsc, const float* __restrict__ bsc,
    float* __restrict__ out_pair, float* __restrict__ out_ctx)
{
    extern __shared__ char smc[];
    __shared__ float s_red[33];

    const int tid = threadIdx.x;
    const int warp = tid >> 5, lane = tid & 31;
    const int wm = warp & 7, wn = warp >> 3;     // 8(m) x 4(n) warp grid
    const int g = lane >> 2, tig = lane & 3;
    const int i = blockIdx.x & 127;
    const int b = blockIdx.x >> 7;

    const uint32_t sbA = s2u(smc);
    const uint32_t sbB = sbA + OFF_B;
    const float* binrow = bin + (size_t)(b * NN + i) * NN * NH;

    float acc[8][4];
#pragma unroll
    for (int x = 0; x < 8; x++)
#pragma unroll
        for (int y = 0; y < 4; y++) acc[x][y] = 0.f;

    auto load_chunk = [&](int c) {
        const int kb = c << 5;
        const int buf = c & 1;
        {   // A: 128 rows x 32 f32, row stride 144B
            int j = tid >> 3, w = tid & 7;
            cp16(sbA + buf * A_BUF + j * 144 + w * 16,
                 binrow + (size_t)j * NH + kb + w * 4);
        }
        {   // B: 256 rows x 32 fp16, row stride 80B
            int n = tid >> 2, w = tid & 3;
            cp16(sbB + buf * B_BUF + n * 80 + w * 16,
                 g_wbinT_h + (size_t)n * NH + kb + w * 8);
        }
        cp_commit();
    };

    load_chunk(0);

    // stage per-column vectors
    if (tid < 64) {
        *(float4*)(smc + OFF_W + tid * 16) = *(const float4*)(wsc + tid * 4);
    } else if (tid < 128) {
        int t = tid - 64;
        *(float4*)(smc + OFF_XI + t * 16) =
            *(const float4*)(g_xwb + (size_t)(b * NN + i) * NH + t * 4);
    }

    // atom_pair streaming store (never re-read -> .cs to keep L2 clean)
    {
        float* po = out_pair + (size_t)(b * NN + i) * NN * NH;
        const float* xi = inp + (size_t)(b * NN + i) * NH;
        const float* xb = inp + (size_t)b * NN * NH;
#pragma unroll 4
        for (int c = tid; c < 8192; c += 1024) {
            int j = c >> 6, h4 = (c & 63) << 2;
            float4 vi = *(const float4*)(xi + h4);
            float4 vj = __ldg((const float4*)(xb + (size_t)j * NH + h4));
            __stcs((float4*)(po + (size_t)j * NH + h4),
                   make_float4(vi.x + vj.x, vi.y + vj.y, vi.z + vj.z, vi.w + vj.w));
        }
    }

#pragma unroll 1
    for (int it = 0; it < 8; it++) {
        if (it < 7) { load_chunk(it + 1); cp_wait<1>(); }
        else        { cp_wait<0>(); }
        __syncthreads();

        const float* As = (const float*)(smc + (it & 1) * A_BUF);
        const char*  Bs = smc + OFF_B + (it & 1) * B_BUF;
#pragma unroll
        for (int ks = 0; ks < 32; ks += 16) {
            uint32_t a[4];
            {
                int r = wm * 16 + g;                    // A stride = 36 floats (144B)
                float2 p0 = *(const float2*)(As + r * 36 + ks + tig * 2);
                float2 p1 = *(const float2*)(As + (r + 8) * 36 + ks + tig * 2);
                float2 p2 = *(const float2*)(As + r * 36 + ks + tig * 2 + 8);
                float2 p3 = *(const float2*)(As + (r + 8) * 36 + ks + tig * 2 + 8);
                a[0] = packh2(p0.x, p0.y);
                a[1] = packh2(p1.x, p1.y);
                a[2] = packh2(p2.x, p2.y);
                a[3] = packh2(p3.x, p3.y);
            }
#pragma unroll
            for (int nt = 0; nt < 8; nt++) {
                int n = wn * 64 + nt * 8 + g;
                uint32_t b0 = *(const uint32_t*)(Bs + n * 80 + (ks + tig * 2) * 2);
                uint32_t b1 = *(const uint32_t*)(Bs + n * 80 + (ks + tig * 2 + 8) * 2);
                mma_f16(acc[nt], a, b0, b1);
            }
        }
        __syncthreads();
    }

    // epilogue: relu(D + xwi + xwj) . w_score, reduce over (j,n)
    const float* sW  = (const float*)(smc + OFF_W);
    const float* sXI = (const float*)(smc + OFF_XI);
    const float* xwb_b = g_xwb + (size_t)b * NN * NH;

    float partial = 0.f;
    {
        int j0 = wm * 16 + g;
        const float* xj0 = xwb_b + (size_t)j0 * NH;
        const float* xj1 = xwb_b + (size_t)(j0 + 8) * NH;
#pragma unroll
        for (int nt = 0; nt < 8; nt++) {
            int k = wn * 64 + nt * 8 + tig * 2;
            float2 w  = *(const float2*)(sW + k);
            float2 xi = *(const float2*)(sXI + k);
            float2 xa = *(const float2*)(xj0 + k);
            float2 xb2 = *(const float2*)(xj1 + k);
            partial = fmaf(fmaxf(acc[nt][0] + xi.x + xa.x, 0.f), w.x, partial);
            partial = fmaf(fmaxf(acc[nt][1] + xi.y + xa.y, 0.f), w.y, partial);
            partial = fmaf(fmaxf(acc[nt][2] + xi.x + xb2.x, 0.f), w.x, partial);
            partial = fmaf(fmaxf(acc[nt][3] + xi.y + xb2.y, 0.f), w.y, partial);
        }
    }
#pragma unroll
    for (int o = 16; o; o >>= 1) partial += __shfl_xor_sync(0xffffffffu, partial, o);
    if (lane == 0) s_red[warp] = partial;
    __syncthreads();
    if (tid == 0) {
        float s = 0.f;
#pragma unroll
        for (int w = 0; w < 32; w++) s += s_red[w];
        s_red[32] = s + 128.f * bsc[0];
    }
    __syncthreads();

    if (tid < NH) {
        const float s = s_red[32];
        out_ctx[(size_t)(b * NN + i) * NH + tid] =
            s * inp[(size_t)(b * NN + i) * NH + tid];
    }
}

// ---------------- launch ----------------
extern "C" void kernel_launch(void* const* d_in, const int* in_sizes, int n_in,
                              void* d_out, int out_size)
{
    const float* inputs  = (const float*)d_in[0];
    const float* bin     = (const float*)d_in[1];
    const float* W_atom  = (const float*)d_in[2];
    const float* W_bin   = (const float*)d_in[3];
    const float* b_bin   = (const float*)d_in[4];
    const float* w_score = (const float*)d_in[5];
    const float* b_score = (const float*)d_in[6];

    float* out_ctx  = (float*)d_out;
    float* out_pair = out_ctx + NB * NN * NH;

    cudaFuncSetAttribute(k_main, cudaFuncAttributeMaxDynamicSharedMemorySize, SMEM_MAIN);

    k_prep<<<320, 256>>>(inputs, W_atom, W_bin, b_bin);
    k_main<<<NB * NN, 1024, SMEM_MAIN>>>(bin, inputs, w_score, b_score,
                                         out_pair, out_ctx);
}

// round 12
// speedup vs baseline: 1.0421x; 1.0421x over previous
#include <cuda_runtime.h>
#include <cuda_fp16.h>
#include <cstdint>

#define NB 16
#define NN 128
#define NH 256

// ---------------- scratch (static, no runtime allocation) ----------------
__device__ float g_xwb[NB * NN * NH];                 // inputs@W_atom + 0.5*b_bin (fp32, 2 MB)
__device__ __align__(16) __half g_wbinT_h[NH * NH];   // W_bin transposed [n][h], fp16 (128 KB)

// ---------------- helpers ----------------
__device__ __forceinline__ uint32_t s2u(const void* p) {
    return (uint32_t)__cvta_generic_to_shared(p);
}
__device__ __forceinline__ void cp16(uint32_t d, const void* s) {
    asm volatile("cp.async.cg.shared.global [%0], [%1], 16;" :: "r"(d), "l"(s));
}
__device__ __forceinline__ void cp_commit() { asm volatile("cp.async.commit_group;"); }
template <int N> __device__ __forceinline__ void cp_wait() {
    asm volatile("cp.async.wait_group %0;" :: "n"(N));
}
__device__ __forceinline__ uint32_t packh2(float x, float y) {
    __half2 h = __floats2half2_rn(x, y);
    return *(uint32_t*)&h;
}
__device__ __forceinline__ void mma_f16(float* c, const uint32_t* a, uint32_t b0, uint32_t b1) {
    asm volatile(
        "mma.sync.aligned.m16n8k16.row.col.f32.f16.f16.f32 "
        "{%0,%1,%2,%3}, {%4,%5,%6,%7}, {%8,%9}, {%0,%1,%2,%3};"
        : "+f"(c[0]), "+f"(c[1]), "+f"(c[2]), "+f"(c[3])
        : "r"(a[0]), "r"(a[1]), "r"(a[2]), "r"(a[3]), "r"(b0), "r"(b1));
}

// ---------------- kernel 1: xwb = inputs@W_atom + 0.5*b_bin ; W_bin^T -> fp16 ----------------
__global__ __launch_bounds__(256) void k_prep(
    const float* __restrict__ inp, const float* __restrict__ Wa,
    const float* __restrict__ Wb, const float* __restrict__ bb)
{
    __shared__ float sh[2112];
    const int tid = threadIdx.x;
    const int bid = blockIdx.x;

    if (bid < 256) {
        const int base = bid * 8;
        for (int c = tid; c < 512; c += 256)
            ((float4*)sh)[c] = ((const float4*)(inp + (size_t)base * NH))[c];
        __syncthreads();

        const int quad = tid & 63;
        const int c0 = quad * 4;
        const int r0 = (tid >> 6) * 2;
        float acc0[4] = {0, 0, 0, 0}, acc1[4] = {0, 0, 0, 0};
        const float* s0 = sh + r0 * NH;
        const float* s1 = sh + (r0 + 1) * NH;
#pragma unroll 4
        for (int h = 0; h < NH; h++) {
            float4 w = *(const float4*)(Wa + (size_t)h * NH + c0);
            float a0 = s0[h], a1 = s1[h];
            acc0[0] = fmaf(a0, w.x, acc0[0]); acc0[1] = fmaf(a0, w.y, acc0[1]);
            acc0[2] = fmaf(a0, w.z, acc0[2]); acc0[3] = fmaf(a0, w.w, acc0[3]);
            acc1[0] = fmaf(a1, w.x, acc1[0]); acc1[1] = fmaf(a1, w.y, acc1[1]);
            acc1[2] = fmaf(a1, w.z, acc1[2]); acc1[3] = fmaf(a1, w.w, acc1[3]);
        }
        float4 bv = *(const float4*)(bb + c0);
        *(float4*)(g_xwb + (size_t)(base + r0) * NH + c0) =
            make_float4(acc0[0] + 0.5f * bv.x, acc0[1] + 0.5f * bv.y,
                        acc0[2] + 0.5f * bv.z, acc0[3] + 0.5f * bv.w);
        *(float4*)(g_xwb + (size_t)(base + r0 + 1) * NH + c0) =
            make_float4(acc1[0] + 0.5f * bv.x, acc1[1] + 0.5f * bv.y,
                        acc1[2] + 0.5f * bv.z, acc1[3] + 0.5f * bv.w);
    } else {
        // transpose 32x32 tile of W_bin -> g_wbinT_h[n][h] (fp16)
        const int t = bid - 256;
        const int nb = (t >> 3) * 32, hb = (t & 7) * 32;
        const int ty = tid >> 5, tx = tid & 31;
#pragma unroll
        for (int r = 0; r < 4; r++) {
            int hl = ty + r * 8;
            sh[hl * 33 + tx] = Wb[(size_t)(hb + hl) * NH + nb + tx];
        }
        __syncthreads();
#pragma unroll
        for (int r = 0; r < 4; r++) {
            int nl = ty + r * 8;
            g_wbinT_h[(size_t)(nb + nl) * NH + hb + tx] = __float2half_rn(sh[tx * 33 + nl]);
        }
    }
}

// ---------------- kernel 2: fp16 MMA GEMM + fused epilogue + atom_pair ----------------
// One CTA per (b,i): D[j,n] = sum_h bin[b,i,j,h]*W_bin[h,n], M=128, N=256, K=256.
// 512 threads = 16 warps in 4(m) x 4(n); warp tile 32x64 (2 m-subtiles) -> max B reuse.
// K chunked by 32, FOUR-stage cp.async ring (3 chunks in flight), 1 barrier/iter.
// SMEM: A f32 [4][128][144B] (73728), B fp16 [4][256][80B] (81920), sW 1KB, sXI 1KB.
#define A_BUF   18432
#define B_BUF   20480
#define OFF_B   73728
#define OFF_W   155648
#define OFF_XI  156672
#define SMEM_MAIN 157696

__global__ __launch_bounds__(512, 1) void k_main(
    const float* __restrict__ bin, const float* __restrict__ inp,
    const float* __restrict__ wsc, const float* __restrict__ bsc,
    float* __restrict__ out_pair, float* __restrict__ out_ctx)
{
    extern __shared__ char smc[];
    __shared__ float s_red[17];

    const int tid = threadIdx.x;
    const int warp = tid >> 5, lane = tid & 31;
    const int wm = warp & 3, wn = warp >> 2;     // 4(m) x 4(n) warp grid
    const int g = lane >> 2, tig = lane & 3;
    const int i = blockIdx.x & 127;
    const int b = blockIdx.x >> 7;

    const uint32_t sbA = s2u(smc);
    const uint32_t sbB = sbA + OFF_B;
    const float* binrow = bin + (size_t)(b * NN + i) * NN * NH;

    float acc[2][8][4];
#pragma unroll
    for (int m = 0; m < 2; m++)
#pragma unroll
        for (int x = 0; x < 8; x++)
#pragma unroll
            for (int y = 0; y < 4; y++) acc[m][x][y] = 0.f;

    auto load_chunk = [&](int c) {
        const int kb = c << 5;
        const int st = c & 3;
#pragma unroll
        for (int u = 0; u < 2; u++) {                 // A: 128x32 f32, row stride 144B
            int idx = tid + u * 512;
            int j = idx >> 3, w = idx & 7;
            cp16(sbA + st * A_BUF + j * 144 + w * 16,
                 binrow + (size_t)j * NH + kb + w * 4);
        }
#pragma unroll
        for (int u = 0; u < 2; u++) {                 // B: 256x32 fp16, row stride 80B
            int idx = tid + u * 512;
            int n = idx >> 2, w = idx & 3;
            cp16(sbB + st * B_BUF + n * 80 + w * 16,
                 g_wbinT_h + (size_t)n * NH + kb + w * 8);
        }
        cp_commit();
    };

    // prologue: 3 chunks in flight
    load_chunk(0);
    load_chunk(1);
    load_chunk(2);

    // stage per-column vectors
    if (tid < 64) {
        *(float4*)(smc + OFF_W + tid * 16) = *(const float4*)(wsc + tid * 4);
    } else if (tid < 128) {
        int t = tid - 64;
        *(float4*)(smc + OFF_XI + t * 16) =
            *(const float4*)(g_xwb + (size_t)(b * NN + i) * NH + t * 4);
    }

    // atom_pair streaming store (never re-read -> .cs keeps L2 clean)
    {
        float* po = out_pair + (size_t)(b * NN + i) * NN * NH;
        const float* xi = inp + (size_t)(b * NN + i) * NH;
        const float* xb = inp + (size_t)b * NN * NH;
#pragma unroll 4
        for (int c = tid; c < 8192; c += 512) {
            int j = c >> 6, h4 = (c & 63) << 2;
            float4 vi = *(const float4*)(xi + h4);
            float4 vj = __ldg((const float4*)(xb + (size_t)j * NH + h4));
            __stcs((float4*)(po + (size_t)j * NH + h4),
                   make_float4(vi.x + vj.x, vi.y + vj.y, vi.z + vj.z, vi.w + vj.w));
        }
    }

#pragma unroll 1
    for (int it = 0; it < 8; it++) {
        // chunks pending: it .. min(it+2,7); drain until chunk it is complete
        if (it < 6)       cp_wait<2>();
        else if (it == 6) cp_wait<1>();
        else              cp_wait<0>();
        __syncthreads();   // tile visible; all warps done reading stage (it-1)&3

        const float* As = (const float*)(smc + (it & 3) * A_BUF);
        const char*  Bs = smc + OFF_B + (it & 3) * B_BUF;
#pragma unroll
        for (int ks = 0; ks < 32; ks += 16) {
            uint32_t a[2][4];
#pragma unroll
            for (int mt = 0; mt < 2; mt++) {
                int r = wm * 32 + mt * 16 + g;
                float2 p0 = *(const float2*)(As + r * 36 + ks + tig * 2);
                float2 p1 = *(const float2*)(As + (r + 8) * 36 + ks + tig * 2);
                float2 p2 = *(const float2*)(As + r * 36 + ks + tig * 2 + 8);
                float2 p3 = *(const float2*)(As + (r + 8) * 36 + ks + tig * 2 + 8);
                a[mt][0] = packh2(p0.x, p0.y);
                a[mt][1] = packh2(p1.x, p1.y);
                a[mt][2] = packh2(p2.x, p2.y);
                a[mt][3] = packh2(p3.x, p3.y);
            }
#pragma unroll
            for (int nt = 0; nt < 8; nt++) {
                int n = wn * 64 + nt * 8 + g;
                uint32_t b0 = *(const uint32_t*)(Bs + n * 80 + (ks + tig * 2) * 2);
                uint32_t b1 = *(const uint32_t*)(Bs + n * 80 + (ks + tig * 2 + 8) * 2);
                mma_f16(acc[0][nt], a[0], b0, b1);
                mma_f16(acc[1][nt], a[1], b0, b1);
            }
        }

        // prefetch chunk it+3 into stage (it+3)&3 = (it-1)&3 (freed by barrier above)
        if (it + 3 < 8) load_chunk(it + 3);
    }

    // epilogue: relu(D + xwi + xwj) . w_score, reduce over (j,n)
    // acc[mt] covers rows j = wm*32 + mt*16 + {g, g+8}  (FIXED: index acc by mt)
    const float* sW  = (const float*)(smc + OFF_W);
    const float* sXI = (const float*)(smc + OFF_XI);
    const float* xwb_b = g_xwb + (size_t)b * NN * NH;

    float partial = 0.f;
#pragma unroll
    for (int mt = 0; mt < 2; mt++) {
        int j0 = wm * 32 + mt * 16 + g;
        const float* xj0 = xwb_b + (size_t)j0 * NH;
        const float* xj1 = xwb_b + (size_t)(j0 + 8) * NH;
#pragma unroll
        for (int nt = 0; nt < 8; nt++) {
            int k = wn * 64 + nt * 8 + tig * 2;
            float2 w  = *(const float2*)(sW + k);
            float2 xi = *(const float2*)(sXI + k);
            float2 xa = *(const float2*)(xj0 + k);
            float2 xb2 = *(const float2*)(xj1 + k);
            partial = fmaf(fmaxf(acc[mt][nt][0] + xi.x + xa.x, 0.f), w.x, partial);
            partial = fmaf(fmaxf(acc[mt][nt][1] + xi.y + xa.y, 0.f), w.y, partial);
            partial = fmaf(fmaxf(acc[mt][nt][2] + xi.x + xb2.x, 0.f), w.x, partial);
            partial = fmaf(fmaxf(acc[mt][nt][3] + xi.y + xb2.y, 0.f), w.y, partial);
        }
    }
#pragma unroll
    for (int o = 16; o; o >>= 1) partial += __shfl_xor_sync(0xffffffffu, partial, o);
    if (lane == 0) s_red[warp] = partial;
    __syncthreads();
    if (tid == 0) {
        float s = 0.f;
#pragma unroll
        for (int w = 0; w < 16; w++) s += s_red[w];
        s_red[16] = s + 128.f * bsc[0];
    }
    __syncthreads();

    if (tid < NH) {
        const float s = s_red[16];
        out_ctx[(size_t)(b * NN + i) * NH + tid] =
            s * inp[(size_t)(b * NN + i) * NH + tid];
    }
}

// ---------------- launch ----------------
extern "C" void kernel_launch(void* const* d_in, const int* in_sizes, int n_in,
                              void* d_out, int out_size)
{
    const float* inputs  = (const float*)d_in[0];
    const float* bin     = (const float*)d_in[1];
    const float* W_atom  = (const float*)d_in[2];
    const float* W_bin   = (const float*)d_in[3];
    const float* b_bin   = (const float*)d_in[4];
    const float* w_score = (const float*)d_in[5];
    const float* b_score = (const float*)d_in[6];

    float* out_ctx  = (float*)d_out;
    float* out_pair = out_ctx + NB * NN * NH;

    cudaFuncSetAttribute(k_main, cudaFuncAttributeMaxDynamicSharedMemorySize, SMEM_MAIN);

    k_prep<<<320, 256>>>(inputs, W_atom, W_bin, b_bin);
    k_main<<<NB * NN, 512, SMEM_MAIN>>>(bin, inputs, w_score, b_score,
                                        out_pair, out_ctx);
}

// round 14
// speedup vs baseline: 1.1523x; 1.1058x over previous
#include <cuda_runtime.h>
#include <cuda_fp16.h>
#include <cstdint>

#define NB 16
#define NN 128
#define NH 256

// ---------------- scratch (static, no runtime allocation) ----------------
__device__ float g_xwb[NB * NN * NH];                    // inputs@W_atom + 0.5*b_bin (fp32, 2 MB)
__device__ __align__(128) __half g_wbin_pre[NH * NH];    // W_bin^T, fp16, swizzled n-major (128 KB)

// ---------------- helpers ----------------
__device__ __forceinline__ uint32_t s2u(const void* p) {
    return (uint32_t)__cvta_generic_to_shared(p);
}
__device__ __forceinline__ uint32_t packh2(float x, float y) {
    __half2 h = __floats2half2_rn(x, y);
    return *(uint32_t*)&h;
}
__device__ __forceinline__ void mma_f16(float* c, const uint32_t* a, uint32_t b0, uint32_t b1) {
    asm volatile(
        "mma.sync.aligned.m16n8k16.row.col.f32.f16.f16.f32 "
        "{%0,%1,%2,%3}, {%4,%5,%6,%7}, {%8,%9}, {%0,%1,%2,%3};"
        : "+f"(c[0]), "+f"(c[1]), "+f"(c[2]), "+f"(c[3])
        : "r"(a[0]), "r"(a[1]), "r"(a[2]), "r"(a[3]), "r"(b0), "r"(b1));
}
__device__ __forceinline__ void ldmx4(uint32_t* r, uint32_t addr) {
    asm volatile("ldmatrix.sync.aligned.m8n8.x4.shared.b16 {%0,%1,%2,%3}, [%4];"
                 : "=r"(r[0]), "=r"(r[1]), "=r"(r[2]), "=r"(r[3]) : "r"(addr));
}
__device__ __forceinline__ void mbar_init(uint32_t a, uint32_t n) {
    asm volatile("mbarrier.init.shared.b64 [%0], %1;" :: "r"(a), "r"(n) : "memory");
}
__device__ __forceinline__ void mbar_expect_tx(uint32_t a, uint32_t bytes) {
    asm volatile("mbarrier.arrive.expect_tx.shared.b64 _, [%0], %1;"
                 :: "r"(a), "r"(bytes) : "memory");
}
__device__ __forceinline__ void mbar_wait(uint32_t a, uint32_t ph) {
    asm volatile("{\n\t.reg .pred P;\n\t"
                 "W%=:\n\t"
                 "mbarrier.try_wait.parity.acquire.cta.shared::cta.b64 P, [%0], %1, 0x989680;\n\t"
                 "@P bra D%=;\n\t"
                 "bra W%=;\n\t"
                 "D%=:\n\t}" :: "r"(a), "r"(ph) : "memory");
}
__device__ __forceinline__ void bulk_g2s(uint32_t dst, const void* src, uint32_t bytes,
                                         uint32_t mbar) {
    asm volatile("cp.async.bulk.shared::cta.global.mbarrier::complete_tx::bytes "
                 "[%0], [%1], %2, [%3];"
                 :: "r"(dst), "l"(src), "r"(bytes), "r"(mbar) : "memory");
}

// Swizzled half-index inside an [row][256 halves = 512B] tile:
//   chunk16B' = (k>>3) ^ (row&7);  off = row*256 + chunk'*8 + (k&7)
__host__ __device__ __forceinline__ int swz_off(int row, int k) {
    return row * 256 + ((((k >> 3) ^ (row & 7)) << 3) | (k & 7));
}

// ---------------- kernel 1: xwb = inputs@W_atom + 0.5*b_bin ; W_bin^T -> swizzled fp16 ----------------
__global__ __launch_bounds__(256) void k_prep(
    const float* __restrict__ inp, const float* __restrict__ Wa,
    const float* __restrict__ Wb, const float* __restrict__ bb)
{
    __shared__ float sh[1089];
    const int tid = threadIdx.x;
    const int bid = blockIdx.x;

    if (bid < 512) {
        // xwb rows [bid*4, bid*4+4)
        const int base = bid * 4;
        if (tid < 256) {
            ((float4*)sh)[tid] = ((const float4*)(inp + (size_t)base * NH))[tid];
        }
        __syncthreads();

        const int c0 = (tid & 63) * 4;
        const int r = tid >> 6;  // 0..3
        float acc0 = 0.f, acc1 = 0.f, acc2 = 0.f, acc3 = 0.f;
        const float* s0 = sh + r * NH;
#pragma unroll 8
        for (int h = 0; h < NH; h++) {
            float4 w = *(const float4*)(Wa + (size_t)h * NH + c0);
            float a = s0[h];
            acc0 = fmaf(a, w.x, acc0); acc1 = fmaf(a, w.y, acc1);
            acc2 = fmaf(a, w.z, acc2); acc3 = fmaf(a, w.w, acc3);
        }
        float4 bv = *(const float4*)(bb + c0);
        *(float4*)(g_xwb + (size_t)(base + r) * NH + c0) =
            make_float4(acc0 + 0.5f * bv.x, acc1 + 0.5f * bv.y,
                        acc2 + 0.5f * bv.z, acc3 + 0.5f * bv.w);
    } else {
        // transpose 32x32 tile of W_bin -> g_wbin_pre[n][k] fp16, swizzled rows
        const int t = bid - 512;
        const int nb = (t >> 3) * 32, hb = (t & 7) * 32;
        const int ty = tid >> 5, tx = tid & 31;
#pragma unroll
        for (int r = 0; r < 4; r++) {
            int hl = ty + r * 8;
            sh[hl * 33 + tx] = Wb[(size_t)(hb + hl) * NH + nb + tx];
        }
        __syncthreads();
#pragma unroll
        for (int r = 0; r < 4; r++) {
            int nl = ty + r * 8;
            int n = nb + nl, k = hb + tx;
            g_wbin_pre[swz_off(n, k)] = __float2half_rn(sh[tx * 33 + nl]);
        }
    }
}

// ---------------- kernel 2: resident-operand HMMA GEMM + fused epilogue + atom_pair ----------------
// One CTA per (b,i). A' = bin row converted to fp16 in smem (64 KB, swizzled).
// B = W_bin^T fp16 (128 KB, swizzled) via ONE cp.async.bulk. 16 warps, 4m x 4n, warp 32x64.
#define OFF_AP  0
#define OFF_B   65536
#define OFF_W   196608
#define OFF_XI  197632
#define SMEM_MAIN 198656

__global__ __launch_bounds__(512, 1) void k_main(
    const float* __restrict__ bin, const float* __restrict__ inp,
    const float* __restrict__ wsc, const float* __restrict__ bsc,
    float* __restrict__ out_pair, float* __restrict__ out_ctx)
{
    extern __shared__ __align__(128) char smc[];
    __shared__ __align__(8) uint64_t s_mbar;
    __shared__ float s_red[17];

    const int tid = threadIdx.x;
    const int warp = tid >> 5, lane = tid & 31;
    const int wm = warp & 3, wn = warp >> 2;     // 4(m) x 4(n) warp grid
    const int g = lane >> 2, tig = lane & 3;
    const int i = blockIdx.x & 127;
    const int b = blockIdx.x >> 7;

    const uint32_t sBase = s2u(smc);
    const uint32_t sAP = sBase + OFF_AP;
    const uint32_t sB  = sBase + OFF_B;
    const uint32_t mb  = s2u(&s_mbar);
    const float* binrow = bin + (size_t)(b * NN + i) * NN * NH;

    // ---- mbarrier init, then kick the B bulk copy ----
    if (tid == 0) mbar_init(mb, 1);
    __syncthreads();
    if (tid == 0) {
        mbar_expect_tx(mb, 131072u);
        bulk_g2s(sB, g_wbin_pre, 131072u, mb);
    }

    // ---- convert A (f32 global) -> A' (fp16 smem, swizzled) ----
    {
        const int j = tid >> 2;          // 0..127
        const int kg = tid & 3;          // 0..3 (64-col group)
        const float* src = binrow + (size_t)j * NH + kg * 64;
        const uint32_t dstBase = sAP + j * 512;
        const uint32_t swzj = (j & 7) << 4;
#pragma unroll
        for (int q = 0; q < 8; q++) {
            int qq = (q + kg * 2) & 7;   // rotation -> conflict-free STS
            float4 v0 = *(const float4*)(src + qq * 8);
            float4 v1 = *(const float4*)(src + qq * 8 + 4);
            uint32_t h0 = packh2(v0.x, v0.y), h1 = packh2(v0.z, v0.w);
            uint32_t h2 = packh2(v1.x, v1.y), h3 = packh2(v1.z, v1.w);
            uint32_t c = (uint32_t)(kg * 8 + qq) << 4;
            uint32_t addr = dstBase + (c ^ swzj);
            asm volatile("st.shared.v4.b32 [%0], {%1,%2,%3,%4};"
                         :: "r"(addr), "r"(h0), "r"(h1), "r"(h2), "r"(h3));
        }
    }

    // ---- stage per-column vectors ----
    if (tid < 64) {
        *(float4*)(smc + OFF_W + tid * 16) = *(const float4*)(wsc + tid * 4);
    } else if (tid < 128) {
        int t = tid - 64;
        *(float4*)(smc + OFF_XI + t * 16) =
            *(const float4*)(g_xwb + (size_t)(b * NN + i) * NH + t * 4);
    }

    // ---- atom_pair streaming store (drains during compute) ----
    {
        float* po = out_pair + (size_t)(b * NN + i) * NN * NH;
        const float* xi = inp + (size_t)(b * NN + i) * NH;
        const float* xb = inp + (size_t)b * NN * NH;
#pragma unroll 4
        for (int c = tid; c < 8192; c += 512) {
            int j = c >> 6, h4 = (c & 63) << 2;
            float4 vi = *(const float4*)(xi + h4);
            float4 vj = __ldg((const float4*)(xb + (size_t)j * NH + h4));
            __stcs((float4*)(po + (size_t)j * NH + h4),
                   make_float4(vi.x + vj.x, vi.y + vj.y, vi.z + vj.z, vi.w + vj.w));
        }
    }

    __syncthreads();          // A' complete
    mbar_wait(mb, 0);         // B complete (acquire)

    // ---- mainloop: K=256, all operands resident ----
    float acc[2][8][4];
#pragma unroll
    for (int m = 0; m < 2; m++)
#pragma unroll
        for (int x = 0; x < 8; x++)
#pragma unroll
            for (int y = 0; y < 4; y++) acc[m][x][y] = 0.f;

    const int l15 = lane & 15;
    const uint32_t hi16 = (uint32_t)(lane >> 4) << 4;  // 0 or 16
    const uint32_t swz = (uint32_t)(lane & 7) << 4;
    const uint32_t aOff0 = sAP + (wm * 32 + l15) * 512;
    const uint32_t aOff1 = aOff0 + 16 * 512;
    uint32_t bOff[4];
#pragma unroll
    for (int p = 0; p < 4; p++) bOff[p] = sB + (wn * 64 + p * 16 + l15) * 512;

#pragma unroll 4
    for (int ks = 0; ks < 256; ks += 16) {
        const uint32_t kx = ((uint32_t)(ks * 2) + hi16) ^ swz;
        uint32_t a0[4], a1[4];
        ldmx4(a0, aOff0 + kx);
        ldmx4(a1, aOff1 + kx);
#pragma unroll
        for (int p = 0; p < 4; p++) {
            uint32_t bb[4];
            ldmx4(bb, bOff[p] + kx);
            mma_f16(acc[0][2 * p],     a0, bb[0], bb[2]);
            mma_f16(acc[0][2 * p + 1], a0, bb[1], bb[3]);
            mma_f16(acc[1][2 * p],     a1, bb[0], bb[2]);
            mma_f16(acc[1][2 * p + 1], a1, bb[1], bb[3]);
        }
    }

    // ---- epilogue: relu(D + xwi + xwj) . w_score, reduce over (j,n) ----
    const float* sW  = (const float*)(smc + OFF_W);
    const float* sXI = (const float*)(smc + OFF_XI);
    const float* xwb_b = g_xwb + (size_t)b * NN * NH;

    float partial = 0.f;
#pragma unroll
    for (int mt = 0; mt < 2; mt++) {
        int j0 = wm * 32 + mt * 16 + g;
        const float* xj0 = xwb_b + (size_t)j0 * NH;
        const float* xj1 = xwb_b + (size_t)(j0 + 8) * NH;
#pragma unroll
        for (int nt = 0; nt < 8; nt++) {
            int k = wn * 64 + nt * 8 + tig * 2;
            float2 w  = *(const float2*)(sW + k);
            float2 xi = *(const float2*)(sXI + k);
            float2 xa = *(const float2*)(xj0 + k);
            float2 xb2 = *(const float2*)(xj1 + k);
            partial = fmaf(fmaxf(acc[mt][nt][0] + xi.x + xa.x, 0.f), w.x, partial);
            partial = fmaf(fmaxf(acc[mt][nt][1] + xi.y + xa.y, 0.f), w.y, partial);
            partial = fmaf(fmaxf(acc[mt][nt][2] + xi.x + xb2.x, 0.f), w.x, partial);
            partial = fmaf(fmaxf(acc[mt][nt][3] + xi.y + xb2.y, 0.f), w.y, partial);
        }
    }
#pragma unroll
    for (int o = 16; o; o >>= 1) partial += __shfl_xor_sync(0xffffffffu, partial, o);
    if (lane == 0) s_red[warp] = partial;
    __syncthreads();
    if (tid == 0) {
        float s = 0.f;
#pragma unroll
        for (int w = 0; w < 16; w++) s += s_red[w];
        s_red[16] = s + 128.f * bsc[0];
    }
    __syncthreads();

    if (tid < NH) {
        const float s = s_red[16];
        out_ctx[(size_t)(b * NN + i) * NH + tid] =
            s * inp[(size_t)(b * NN + i) * NH + tid];
    }
}

// ---------------- launch ----------------
extern "C" void kernel_launch(void* const* d_in, const int* in_sizes, int n_in,
                              void* d_out, int out_size)
{
    const float* inputs  = (const float*)d_in[0];
    const float* bin     = (const float*)d_in[1];
    const float* W_atom  = (const float*)d_in[2];
    const float* W_bin   = (const float*)d_in[3];
    const float* b_bin   = (const float*)d_in[4];
    const float* w_score = (const float*)d_in[5];
    const float* b_score = (const float*)d_in[6];

    float* out_ctx  = (float*)d_out;
    float* out_pair = out_ctx + NB * NN * NH;

    cudaFuncSetAttribute(k_main, cudaFuncAttributeMaxDynamicSharedMemorySize, SMEM_MAIN);

    k_prep<<<576, 256>>>(inputs, W_atom, W_bin, b_bin);
    k_main<<<NB * NN, 512, SMEM_MAIN>>>(bin, inputs, w_score, b_score,
                                        out_pair, out_ctx);
}

// round 16
// speedup vs baseline: 1.1899x; 1.0326x over previous
#include <cuda_runtime.h>
#include <cuda_fp16.h>
#include <cstdint>

#define NB 16
#define NN 128
#define NH 256

// ---------------- scratch (static, no runtime allocation) ----------------
__device__ float g_xwb[NB * NN * NH];                    // inputs@W_atom + 0.5*b_bin (fp32, 2 MB)
__device__ __align__(128) __half g_wbin_pre[NH * NH];    // W_bin^T, fp16, swizzled n-major (128 KB)

// ---------------- helpers ----------------
__device__ __forceinline__ uint32_t s2u(const void* p) {
    return (uint32_t)__cvta_generic_to_shared(p);
}
__device__ __forceinline__ uint32_t packh2(float x, float y) {
    __half2 h = __floats2half2_rn(x, y);
    return *(uint32_t*)&h;
}
__device__ __forceinline__ void mma_f16(float* c, const uint32_t* a, uint32_t b0, uint32_t b1) {
    asm volatile(
        "mma.sync.aligned.m16n8k16.row.col.f32.f16.f16.f32 "
        "{%0,%1,%2,%3}, {%4,%5,%6,%7}, {%8,%9}, {%0,%1,%2,%3};"
        : "+f"(c[0]), "+f"(c[1]), "+f"(c[2]), "+f"(c[3])
        : "r"(a[0]), "r"(a[1]), "r"(a[2]), "r"(a[3]), "r"(b0), "r"(b1));
}
__device__ __forceinline__ void ldmx4(uint32_t* r, uint32_t addr) {
    asm volatile("ldmatrix.sync.aligned.m8n8.x4.shared.b16 {%0,%1,%2,%3}, [%4];"
                 : "=r"(r[0]), "=r"(r[1]), "=r"(r[2]), "=r"(r[3]) : "r"(addr));
}
__device__ __forceinline__ void mbar_init(uint32_t a, uint32_t n) {
    asm volatile("mbarrier.init.shared.b64 [%0], %1;" :: "r"(a), "r"(n) : "memory");
}
__device__ __forceinline__ void mbar_expect_tx(uint32_t a, uint32_t bytes) {
    asm volatile("mbarrier.arrive.expect_tx.shared.b64 _, [%0], %1;"
                 :: "r"(a), "r"(bytes) : "memory");
}
__device__ __forceinline__ void mbar_wait(uint32_t a, uint32_t ph) {
    asm volatile("{\n\t.reg .pred P;\n\t"
                 "W%=:\n\t"
                 "mbarrier.try_wait.parity.acquire.cta.shared::cta.b64 P, [%0], %1, 0x989680;\n\t"
                 "@P bra D%=;\n\t"
                 "bra W%=;\n\t"
                 "D%=:\n\t}" :: "r"(a), "r"(ph) : "memory");
}
__device__ __forceinline__ void bulk_g2s(uint32_t dst, const void* src, uint32_t bytes,
                                         uint32_t mbar) {
    asm volatile("cp.async.bulk.shared::cta.global.mbarrier::complete_tx::bytes "
                 "[%0], [%1], %2, [%3];"
                 :: "r"(dst), "l"(src), "r"(bytes), "r"(mbar) : "memory");
}

// Swizzled half-index inside an [row][256 halves = 512B] tile
__host__ __device__ __forceinline__ int swz_off(int row, int k) {
    return row * 256 + ((((k >> 3) ^ (row & 7)) << 3) | (k & 7));
}

// ---------------- kernel 1: xwb = inputs@W_atom + 0.5*b_bin ; W_bin^T -> swizzled fp16 ----------------
__global__ __launch_bounds__(256) void k_prep(
    const float* __restrict__ inp, const float* __restrict__ Wa,
    const float* __restrict__ Wb, const float* __restrict__ bb)
{
    __shared__ float sh[1089];
    const int tid = threadIdx.x;
    const int bid = blockIdx.x;

    if (bid < 512) {
        const int base = bid * 4;
        if (tid < 256) {
            ((float4*)sh)[tid] = ((const float4*)(inp + (size_t)base * NH))[tid];
        }
        __syncthreads();

        const int c0 = (tid & 63) * 4;
        const int r = tid >> 6;
        float acc0 = 0.f, acc1 = 0.f, acc2 = 0.f, acc3 = 0.f;
        const float* s0 = sh + r * NH;
#pragma unroll 8
        for (int h = 0; h < NH; h++) {
            float4 w = *(const float4*)(Wa + (size_t)h * NH + c0);
            float a = s0[h];
            acc0 = fmaf(a, w.x, acc0); acc1 = fmaf(a, w.y, acc1);
            acc2 = fmaf(a, w.z, acc2); acc3 = fmaf(a, w.w, acc3);
        }
        float4 bv = *(const float4*)(bb + c0);
        *(float4*)(g_xwb + (size_t)(base + r) * NH + c0) =
            make_float4(acc0 + 0.5f * bv.x, acc1 + 0.5f * bv.y,
                        acc2 + 0.5f * bv.z, acc3 + 0.5f * bv.w);
    } else {
        // transpose 32x32 tile of W_bin -> g_wbin_pre[n][k] fp16, swizzled rows
        const int t = bid - 512;
        const int nb = (t >> 3) * 32, hb = (t & 7) * 32;
        const int ty = tid >> 5, tx = tid & 31;
#pragma unroll
        for (int r = 0; r < 4; r++) {
            int hl = ty + r * 8;
            sh[hl * 33 + tx] = Wb[(size_t)(hb + hl) * NH + nb + tx];
        }
        __syncthreads();
#pragma unroll
        for (int r = 0; r < 4; r++) {
            int nl = ty + r * 8;
            int n = nb + nl, k = hb + tx;
            g_wbin_pre[swz_off(n, k)] = __float2half_rn(sh[tx * 33 + nl]);
        }
    }
}

// ---------------- kernel 2: M-half pipelined HMMA GEMM + fused epilogue + atom_pair ----------------
// One CTA per (b,i). A split into two 64-row halves; LDG(regs)->cvt->STS pipelined
// against mainloop of the other half. B = W_bin^T fp16 via one cp.async.bulk.
// 16 warps 4m x 4n, warp tile 16x64 over M=64 per half.
#define OFF_B   65536
#define OFF_W   196608
#define OFF_XI  197632
#define SMEM_MAIN 198656

__global__ __launch_bounds__(512, 1) void k_main(
    const float* __restrict__ bin, const float* __restrict__ inp,
    const float* __restrict__ wsc, const float* __restrict__ bsc,
    float* __restrict__ out_pair, float* __restrict__ out_ctx)
{
    extern __shared__ __align__(128) char smc[];
    __shared__ __align__(8) uint64_t s_mbar;
    __shared__ float s_red[17];

    const int tid = threadIdx.x;
    const int warp = tid >> 5, lane = tid & 31;
    const int wm = warp & 3, wn = warp >> 2;     // 4(m) x 4(n) warp grid
    const int g = lane >> 2, tig = lane & 3;
    const int l15 = lane & 15;
    const int i = blockIdx.x & 127;
    const int b = blockIdx.x >> 7;

    const uint32_t sAP = s2u(smc);               // A' halves: [2][64][512B] = 64 KB
    const uint32_t sB  = sAP + OFF_B;
    const uint32_t mb  = s2u(&s_mbar);
    const float* binrow = bin + (size_t)(b * NN + i) * NN * NH;

    if (tid == 0) mbar_init(mb, 1);
    __syncthreads();
    if (tid == 0) {
        mbar_expect_tx(mb, 131072u);
        bulk_g2s(sB, g_wbin_pre, 131072u, mb);
    }

    // ---- LDG half0 into registers (coalesced linear float4) ----
    float4 ar[8];
    {
        const float4* s0 = (const float4*)binrow;
#pragma unroll
        for (int q = 0; q < 8; q++) ar[q] = __ldg(s0 + q * 512 + tid);
    }

    // ---- atom_pair streaming store (covers half0 LDG latency) ----
    {
        float* po = out_pair + (size_t)(b * NN + i) * NN * NH;
        const float* xi = inp + (size_t)(b * NN + i) * NH;
        const float* xb = inp + (size_t)b * NN * NH;
#pragma unroll 4
        for (int c = tid; c < 8192; c += 512) {
            int j = c >> 6, h4 = (c & 63) << 2;
            float4 vi = *(const float4*)(xi + h4);
            float4 vj = __ldg((const float4*)(xb + (size_t)j * NH + h4));
            __stcs((float4*)(po + (size_t)j * NH + h4),
                   make_float4(vi.x + vj.x, vi.y + vj.y, vi.z + vj.z, vi.w + vj.w));
        }
    }

    // ---- cvt + STS: regs -> swizzled fp16 half buffer ----
    auto sts_half = [&](uint32_t base) {
#pragma unroll
        for (int q = 0; q < 8; q++) {
            int idx = q * 512 + tid;
            int row = idx >> 6, c2 = idx & 63;     // c2: float4 index in row (64/row)
            uint32_t off = ((uint32_t)(((c2 >> 1) ^ (row & 7)) << 4)) |
                           ((uint32_t)(idx & 1) << 3);
            uint32_t h0 = packh2(ar[q].x, ar[q].y);
            uint32_t h1 = packh2(ar[q].z, ar[q].w);
            asm volatile("st.shared.v2.b32 [%0], {%1,%2};"
                         :: "r"(base + row * 512 + off), "r"(h0), "r"(h1));
        }
    };
    sts_half(sAP);  // half0 -> buffer 0

    // ---- stage per-column vectors ----
    if (tid < 64) {
        *(float4*)(smc + OFF_W + tid * 16) = *(const float4*)(wsc + tid * 4);
    } else if (tid < 128) {
        int t = tid - 64;
        *(float4*)(smc + OFF_XI + t * 16) =
            *(const float4*)(g_xwb + (size_t)(b * NN + i) * NH + t * 4);
    }

    __syncthreads();   // half0 A' visible

    // ---- LDG half1 (latency hidden under mainloop half0) ----
    {
        const float4* s1 = (const float4*)(binrow + 16384);
#pragma unroll
        for (int q = 0; q < 8; q++) ar[q] = __ldg(s1 + q * 512 + tid);
    }

    mbar_wait(mb, 0);  // B resident

    // ---- mainloop machinery ----
    float acc[8][4];
#pragma unroll
    for (int x = 0; x < 8; x++)
#pragma unroll
        for (int y = 0; y < 4; y++) acc[x][y] = 0.f;

    const uint32_t hi16 = (uint32_t)(lane >> 4) << 4;
    const uint32_t swz = (uint32_t)(lane & 7) << 4;
    const uint32_t aRow = sAP + (wm * 16 + l15) * 512;
    uint32_t bOff[4];
#pragma unroll
    for (int p = 0; p < 4; p++) bOff[p] = sB + (wn * 64 + p * 16 + l15) * 512;

    auto mainloop = [&](uint32_t aBase) {
#pragma unroll 4
        for (int ks = 0; ks < 256; ks += 16) {
            const uint32_t kx = ((uint32_t)(ks * 2) + hi16) ^ swz;
            uint32_t a[4];
            ldmx4(a, aBase + kx);
#pragma unroll
            for (int p = 0; p < 4; p++) {
                uint32_t bq[4];
                ldmx4(bq, bOff[p] + kx);
                mma_f16(acc[2 * p],     a, bq[0], bq[2]);
                mma_f16(acc[2 * p + 1], a, bq[1], bq[3]);
            }
        }
    };

    const float* sW  = (const float*)(smc + OFF_W);
    const float* sXI = (const float*)(smc + OFF_XI);
    const float* xwb_b = g_xwb + (size_t)b * NN * NH;
    float partial = 0.f;

    auto epi = [&](int j0) {
        const float* xj0 = xwb_b + (size_t)j0 * NH;
        const float* xj1 = xwb_b + (size_t)(j0 + 8) * NH;
#pragma unroll
        for (int nt = 0; nt < 8; nt++) {
            int k = wn * 64 + nt * 8 + tig * 2;
            float2 w  = *(const float2*)(sW + k);
            float2 xi = *(const float2*)(sXI + k);
            float2 xa = *(const float2*)(xj0 + k);
            float2 xb2 = *(const float2*)(xj1 + k);
            partial = fmaf(fmaxf(acc[nt][0] + xi.x + xa.x, 0.f), w.x, partial);
            partial = fmaf(fmaxf(acc[nt][1] + xi.y + xa.y, 0.f), w.y, partial);
            partial = fmaf(fmaxf(acc[nt][2] + xi.x + xb2.x, 0.f), w.x, partial);
            partial = fmaf(fmaxf(acc[nt][3] + xi.y + xb2.y, 0.f), w.y, partial);
        }
    };

    // ---- half0 compute ----
    mainloop(aRow);            // buffer 0
    sts_half(sAP + 32768);     // write half1 buffer (frees ar)
    epi(wm * 16 + g);          // half0 rows: j in [0,64)
#pragma unroll
    for (int x = 0; x < 8; x++)
#pragma unroll
        for (int y = 0; y < 4; y++) acc[x][y] = 0.f;

    __syncthreads();           // half1 A' visible

    // ---- half1 compute ----
    mainloop(aRow + 32768);
    epi(64 + wm * 16 + g);     // half1 rows: j in [64,128)

    // ---- reduce + ctx ----
#pragma unroll
    for (int o = 16; o; o >>= 1) partial += __shfl_xor_sync(0xffffffffu, partial, o);
    if (lane == 0) s_red[warp] = partial;
    __syncthreads();
    if (tid == 0) {
        float s = 0.f;
#pragma unroll
        for (int w = 0; w < 16; w++) s += s_red[w];
        s_red[16] = s + 128.f * bsc[0];
    }
    __syncthreads();

    if (tid < NH) {
        const float s = s_red[16];
        out_ctx[(size_t)(b * NN + i) * NH + tid] =
            s * inp[(size_t)(b * NN + i) * NH + tid];
    }
}

// ---------------- launch ----------------
extern "C" void kernel_launch(void* const* d_in, const int* in_sizes, int n_in,
                              void* d_out, int out_size)
{
    const float* inputs  = (const float*)d_in[0];
    const float* bin     = (const float*)d_in[1];
    const float* W_atom  = (const float*)d_in[2];
    const float* W_bin   = (const float*)d_in[3];
    const float* b_bin   = (const float*)d_in[4];
    const float* w_score = (const float*)d_in[5];
    const float* b_score = (const float*)d_in[6];

    float* out_ctx  = (float*)d_out;
    float* out_pair = out_ctx + NB * NN * NH;

    cudaFuncSetAttribute(k_main, cudaFuncAttributeMaxDynamicSharedMemorySize, SMEM_MAIN);

    k_prep<<<576, 256>>>(inputs, W_atom, W_bin, b_bin);
    k_main<<<NB * NN, 512, SMEM_MAIN>>>(bin, inputs, w_score, b_score,
                                        out_pair, out_ctx);
}